// round 9
// baseline (speedup 1.0000x reference)
#include <cuda_runtime.h>
#include <cuda_bf16.h>
#include <math.h>
#include <stdint.h>

#define NB 256
#define NI 1152
#define NJ 10
#define NJD 160
#define XSTR 9216
#define KSPLIT 72

__device__ float g_pp[KSPLIT*NB*NJD];
__device__ float g_pp2[6][NB*NJD];
__device__ float g_plb[2][2][NI*NJ];             /* [iter][kchunk][i*10+j] */
__device__ __nv_bfloat16 g_xhi[NB*XSTR];         /* [b][m]  */
__device__ __nv_bfloat16 g_xlo[NB*XSTR];
__device__ __nv_bfloat16 g_xthi[XSTR*NB];        /* [m][b]  */
__device__ __nv_bfloat16 g_xtlo[XSTR*NB];
__device__ __nv_bfloat16 g_sthi[NJD*NB];         /* [jd][b] */
__device__ __nv_bfloat16 g_stlo[NJD*NB];

__device__ __forceinline__ void mma16816(float* c, const unsigned* a,
                                         unsigned b0, unsigned b1) {
    asm volatile("mma.sync.aligned.m16n8k16.row.col.f32.bf16.bf16.f32 "
                 "{%0,%1,%2,%3}, {%4,%5,%6,%7}, {%8,%9}, {%0,%1,%2,%3};"
                 : "+f"(c[0]), "+f"(c[1]), "+f"(c[2]), "+f"(c[3])
                 : "r"(a[0]), "r"(a[1]), "r"(a[2]), "r"(a[3]), "r"(b0), "r"(b1));
}
__device__ __forceinline__ void split_bf(float v, __nv_bfloat16& h, __nv_bfloat16& l) {
    h = __float2bfloat16_rn(v);
    l = __float2bfloat16_rn(v - __bfloat162float(h));
}

/* fused prep: one x read -> row-major hi/lo AND transposed hi/lo */
__global__ __launch_bounds__(256) void k_prep(const float* __restrict__ x) {
    __shared__ float s[32][33];
    const int m0 = blockIdx.x*32, b0 = blockIdx.y*32;
    const int tid = threadIdx.x, tm = tid & 31, tr = tid >> 5;
#pragma unroll
    for (int q = 0; q < 4; q++) {
        int bl = tr + q*8;
        s[bl][tm] = x[(size_t)(b0+bl)*XSTR + m0 + tm];
    }
    __syncthreads();
#pragma unroll
    for (int q = 0; q < 4; q++) {          /* row-major hi/lo */
        int bl = tr + q*8;
        float v = s[bl][tm];
        __nv_bfloat16 h, l; split_bf(v, h, l);
        size_t o = (size_t)(b0+bl)*XSTR + m0 + tm;
        g_xhi[o] = h; g_xlo[o] = l;
    }
#pragma unroll
    for (int q = 0; q < 4; q++) {          /* transposed hi/lo */
        int ml = tr + q*8;
        float v = s[tm][ml];
        __nv_bfloat16 h, l; split_bf(v, h, l);
        size_t o = (size_t)(m0+ml)*NB + b0 + tm;
        g_xthi[o] = h; g_xtlo[o] = l;
    }
}

/* ------------------------------------------------------------------ */
/* k_gemm: pp[ks][b][jd] = sum_{k in slice} x[b,k] * (c(.)W)[jd,k]     */
/* softmax (from plb sums) + B build (c*W split) fused in prologue.    */
/* ------------------------------------------------------------------ */
#define RS 136
#define A_HI 0
#define A_LO (128*RS)
#define B_HI (2*128*RS)
#define B_LO (2*128*RS + 160*RS)
#define GEMM_SMEM ((2*128*RS + 2*160*RS) * 2)

__global__ __launch_bounds__(256,1) void k_gemm(const float* __restrict__ W, int it) {
    extern __shared__ __align__(16) __nv_bfloat16 sb[];
    __shared__ float c_sm[160];
    const int mt = blockIdx.x, ks = blockIdx.y;
    const int tid = threadIdx.x, w = tid >> 5, lane = tid & 31;
    const int g = lane >> 2, tg = lane & 3;
    const int nh = w >> 2, mp = w & 3;
    const int k0 = ks*128, i0 = ks*16;

    if (tid < 16) {
        int i = i0 + tid;
        float l[NJ];
        float m = -1e30f;
#pragma unroll
        for (int j = 0; j < NJ; j++) {
            float v = 0.f;
            for (int t = 0; t < it; t++)
                v += g_plb[t][0][i*NJ+j] + g_plb[t][1][i*NJ+j];
            l[j] = v; m = fmaxf(m, v);
        }
        float ssum = 0.f;
#pragma unroll
        for (int j = 0; j < NJ; j++) { l[j] = expf(l[j]-m); ssum += l[j]; }
        float inv = 1.f/ssum;
#pragma unroll
        for (int j = 0; j < NJ; j++) c_sm[tid*NJ + j] = l[j]*inv;
    }
    __syncthreads();

    for (int idx = tid; idx < 2048; idx += 256) {
        int r = idx >> 4, c4 = idx & 15;
        size_t src = (size_t)(mt*128 + r)*XSTR + k0 + c4*8;
        *(float4*)(sb + A_HI + r*RS + c4*8) = *(const float4*)(g_xhi + src);
        *(float4*)(sb + A_LO + r*RS + c4*8) = *(const float4*)(g_xlo + src);
    }
    for (int idx = tid; idx < 5120; idx += 256) {
        int il = idx / 320, rem = idx - il*320;
        int j = rem >> 5, r2 = rem & 31, d = r2 >> 1, dph = r2 & 1;
        float4 wv = *(const float4*)(W + (size_t)(i0+il)*1280 + j*128 + d*8 + dph*4);
        float c = c_sm[il*NJ + j];
        wv.x *= c; wv.y *= c; wv.z *= c; wv.w *= c;
        __nv_bfloat16 h0,h1,h2,h3,l0,l1,l2,l3;
        split_bf(wv.x,h0,l0); split_bf(wv.y,h1,l1); split_bf(wv.z,h2,l2); split_bf(wv.w,h3,l3);
        int off = (j*16 + d)*RS + il*8 + dph*4;
        *(__nv_bfloat162*)(sb + B_HI + off)     = __nv_bfloat162(h0,h1);
        *(__nv_bfloat162*)(sb + B_HI + off + 2) = __nv_bfloat162(h2,h3);
        *(__nv_bfloat162*)(sb + B_LO + off)     = __nv_bfloat162(l0,l1);
        *(__nv_bfloat162*)(sb + B_LO + off + 2) = __nv_bfloat162(l2,l3);
    }
    __syncthreads();

    float acc[2][10][4];
#pragma unroll
    for (int s = 0; s < 2; s++)
#pragma unroll
        for (int t = 0; t < 10; t++)
#pragma unroll
            for (int r = 0; r < 4; r++) acc[s][t][r] = 0.f;

    const int aoffs[3] = {A_HI, A_HI, A_LO};
    const int boffs[3] = {B_HI, B_LO, B_HI};
#pragma unroll
    for (int p = 0; p < 3; p++) {
        const __nv_bfloat16* Ab = sb + aoffs[p] + (mp*32)*RS;
        const __nv_bfloat16* Bb = sb + boffs[p] + (nh*80 + g)*RS + tg*2;
#pragma unroll
        for (int kk = 0; kk < 8; kk++) {
            unsigned a[2][4];
#pragma unroll
            for (int s = 0; s < 2; s++) {
                const __nv_bfloat16* ap = Ab + s*16*RS + kk*16 + tg*2;
                a[s][0] = *(const unsigned*)(ap + g*RS);
                a[s][1] = *(const unsigned*)(ap + (g+8)*RS);
                a[s][2] = *(const unsigned*)(ap + g*RS + 8);
                a[s][3] = *(const unsigned*)(ap + (g+8)*RS + 8);
            }
#pragma unroll
            for (int t = 0; t < 10; t++) {
                const __nv_bfloat16* bp = Bb + t*8*RS + kk*16;
                unsigned b0 = *(const unsigned*)(bp);
                unsigned b1 = *(const unsigned*)(bp + 8);
                mma16816(acc[0][t], a[0], b0, b1);
                mma16816(acc[1][t], a[1], b0, b1);
            }
        }
    }

    float* base = g_pp + (size_t)ks*NB*NJD;
#pragma unroll
    for (int s = 0; s < 2; s++) {
        int m0 = mt*128 + (mp*2 + s)*16;
#pragma unroll
        for (int t = 0; t < 10; t++) {
            int jd = nh*80 + t*8 + tg*2;
            *(float2*)(base + (size_t)(m0+g)*NJD + jd)   = make_float2(acc[s][t][0], acc[s][t][1]);
            *(float2*)(base + (size_t)(m0+g+8)*NJD + jd) = make_float2(acc[s][t][2], acc[s][t][3]);
        }
    }
}

/* reduce stage 1: sum 12 slices per k-chunk, fully coalesced float4 */
__global__ __launch_bounds__(256) void k_red1() {
    const int idx4 = blockIdx.x*256 + threadIdx.x;   /* 0..10239 */
    const int kc = blockIdx.y;
    const float4* base = (const float4*)g_pp + (size_t)(kc*12)*10240 + idx4;
    float4 a0 = make_float4(0,0,0,0), a1 = a0, a2 = a0, a3 = a0;
#pragma unroll
    for (int t = 0; t < 12; t += 4) {
        float4 v0 = base[(size_t)(t+0)*10240];
        float4 v1 = base[(size_t)(t+1)*10240];
        float4 v2 = base[(size_t)(t+2)*10240];
        float4 v3 = base[(size_t)(t+3)*10240];
        a0.x+=v0.x; a0.y+=v0.y; a0.z+=v0.z; a0.w+=v0.w;
        a1.x+=v1.x; a1.y+=v1.y; a1.z+=v1.z; a1.w+=v1.w;
        a2.x+=v2.x; a2.y+=v2.y; a2.z+=v2.z; a2.w+=v2.w;
        a3.x+=v3.x; a3.y+=v3.y; a3.z+=v3.z; a3.w+=v3.w;
    }
    float4 r;
    r.x = (a0.x+a1.x)+(a2.x+a3.x);
    r.y = (a0.y+a1.y)+(a2.y+a3.y);
    r.z = (a0.z+a1.z)+(a2.z+a3.z);
    r.w = (a0.w+a1.w)+(a2.w+a3.w);
    ((float4*)g_pp2[kc])[idx4] = r;
}

/* reduce stage 2: sum 6 chunks + squash; emit out or transposed s hi/lo */
__global__ __launch_bounds__(160) void k_red2(float* __restrict__ outp, int final_it) {
    const int b = blockIdx.x, jd = threadIdx.x;
    const int idx = b*NJD + jd;
    float v = 0.f;
#pragma unroll
    for (int kc = 0; kc < 6; kc++) v += g_pp2[kc][idx];
    float ss = v*v;
    ss += __shfl_xor_sync(~0u, ss, 1);
    ss += __shfl_xor_sync(~0u, ss, 2);
    ss += __shfl_xor_sync(~0u, ss, 4);
    ss += __shfl_xor_sync(~0u, ss, 8);
    float f = sqrtf(ss)/(1.f + ss);
    float r = v*f;
    if (final_it) { outp[idx] = r; return; }
    __nv_bfloat16 h, l; split_bf(r, h, l);
    g_sthi[jd*NB + b] = h;
    g_stlo[jd*NB + b] = l;
}

/* ------------------------------------------------------------------ */
/* k_agree: Amat[m][jd] = sum_{b chunk} xt[m][b] st[jd][b]  (HMMA),    */
/* then pl[it][kc][i,j] = sum_{d,dp} W[i,j,d,dp] Amat[i*8+dp][j*16+d]. */
/* ------------------------------------------------------------------ */
__global__ __launch_bounds__(256,1) void k_agree(const float* __restrict__ W, int it) {
    extern __shared__ __align__(16) __nv_bfloat16 sb[];
    const int a_ = blockIdx.x, kc = blockIdx.y;
    const int tid = threadIdx.x, w = tid >> 5, lane = tid & 31;
    const int g = lane >> 2, tg = lane & 3;
    const int nh = w >> 2, mp = w & 3;

    for (int idx = tid; idx < 2048; idx += 256) {
        int r = idx >> 4, c4 = idx & 15;
        size_t src = (size_t)(a_*128 + r)*NB + kc*128 + c4*8;
        *(float4*)(sb + A_HI + r*RS + c4*8) = *(const float4*)(g_xthi + src);
        *(float4*)(sb + A_LO + r*RS + c4*8) = *(const float4*)(g_xtlo + src);
    }
    for (int idx = tid; idx < 2560; idx += 256) {
        int r = idx >> 4, c4 = idx & 15;
        size_t src = (size_t)r*NB + kc*128 + c4*8;
        *(float4*)(sb + B_HI + r*RS + c4*8) = *(const float4*)(g_sthi + src);
        *(float4*)(sb + B_LO + r*RS + c4*8) = *(const float4*)(g_stlo + src);
    }
    __syncthreads();

    float acc[2][10][4];
#pragma unroll
    for (int s = 0; s < 2; s++)
#pragma unroll
        for (int t = 0; t < 10; t++)
#pragma unroll
            for (int r = 0; r < 4; r++) acc[s][t][r] = 0.f;

    const int aoffs[3] = {A_HI, A_HI, A_LO};
    const int boffs[3] = {B_HI, B_LO, B_HI};
#pragma unroll
    for (int p = 0; p < 3; p++) {
        const __nv_bfloat16* Ab = sb + aoffs[p] + (mp*32)*RS;
        const __nv_bfloat16* Bb = sb + boffs[p] + (nh*80 + g)*RS + tg*2;
#pragma unroll
        for (int kk = 0; kk < 8; kk++) {
            unsigned a[2][4];
#pragma unroll
            for (int s = 0; s < 2; s++) {
                const __nv_bfloat16* ap = Ab + s*16*RS + kk*16 + tg*2;
                a[s][0] = *(const unsigned*)(ap + g*RS);
                a[s][1] = *(const unsigned*)(ap + (g+8)*RS);
                a[s][2] = *(const unsigned*)(ap + g*RS + 8);
                a[s][3] = *(const unsigned*)(ap + (g+8)*RS + 8);
            }
#pragma unroll
            for (int t = 0; t < 10; t++) {
                const __nv_bfloat16* bp = Bb + t*8*RS + kk*16;
                unsigned b0 = *(const unsigned*)(bp);
                unsigned b1 = *(const unsigned*)(bp + 8);
                mma16816(acc[0][t], a[0], b0, b1);
                mma16816(acc[1][t], a[1], b0, b1);
            }
        }
    }
    __syncthreads();

    float* At = (float*)sb;          /* [128][160] */
#pragma unroll
    for (int s = 0; s < 2; s++) {
        int m0 = (mp*2 + s)*16;
#pragma unroll
        for (int t = 0; t < 10; t++) {
            int jd = nh*80 + t*8 + tg*2;
            *(float2*)(At + (m0+g)*NJD + jd)   = make_float2(acc[s][t][0], acc[s][t][1]);
            *(float2*)(At + (m0+g+8)*NJD + jd) = make_float2(acc[s][t][2], acc[s][t][3]);
        }
    }
    __syncthreads();

    if (tid < 160) {
        int il = tid / NJ, j = tid - il*NJ;
        int i = a_*16 + il;
        float accv = 0.f;
#pragma unroll
        for (int d = 0; d < 16; d++) {
            float4 w0 = *(const float4*)(W + (size_t)i*1280 + j*128 + d*8);
            float4 w1 = *(const float4*)(W + (size_t)i*1280 + j*128 + d*8 + 4);
            const float* ap = At + (il*8)*NJD + j*16 + d;
            accv += w0.x*ap[0*NJD] + w0.y*ap[1*NJD] + w0.z*ap[2*NJD] + w0.w*ap[3*NJD]
                  + w1.x*ap[4*NJD] + w1.y*ap[5*NJD] + w1.z*ap[6*NJD] + w1.w*ap[7*NJD];
        }
        g_plb[it][kc][i*NJ + j] = accv;
    }
}

extern "C" void kernel_launch(void* const* d_in, const int* in_sizes, int n_in,
                              void* d_out, int out_size) {
    const float* x = (const float*)d_in[0];
    const float* W = (const float*)d_in[1];
    float* out = (float*)d_out;

    cudaFuncSetAttribute(k_gemm,  cudaFuncAttributeMaxDynamicSharedMemorySize, GEMM_SMEM);
    cudaFuncSetAttribute(k_agree, cudaFuncAttributeMaxDynamicSharedMemorySize, GEMM_SMEM);

    k_prep<<<dim3(288, 8), 256>>>(x);
    for (int it = 0; it < 3; it++) {
        k_gemm<<<dim3(2, KSPLIT), 256, GEMM_SMEM>>>(W, it);
        k_red1<<<dim3(40, 6), 256>>>();
        k_red2<<<256, 160>>>(out, (it == 2) ? 1 : 0);
        if (it < 2) k_agree<<<dim3(72, 2), 256, GEMM_SMEM>>>(W, it);
    }
}

// round 10
// speedup vs baseline: 1.1586x; 1.1586x over previous
#include <cuda_runtime.h>
#include <cuda_bf16.h>
#include <math.h>
#include <stdint.h>

#define NB 256
#define NI 1152
#define NJ 10
#define NJD 160
#define XSTR 9216
#define KSPLIT 72
#define NCTA 144

__device__ float g_pp[KSPLIT*NB*NJD];
__device__ float g_plb[2][2][NI*NJ];             /* [iter][kchunk][i*10+j] */
__device__ __nv_bfloat16 g_xhi[NB*XSTR];         /* [b][m]  */
__device__ __nv_bfloat16 g_xlo[NB*XSTR];
__device__ __nv_bfloat16 g_xthi[XSTR*NB];        /* [m][b]  */
__device__ __nv_bfloat16 g_xtlo[XSTR*NB];
__device__ __nv_bfloat16 g_sthi[NJD*NB];         /* [jd][b] */
__device__ __nv_bfloat16 g_stlo[NJD*NB];
__device__ unsigned g_arrive;

__device__ __forceinline__ void mma16816(float* c, const unsigned* a,
                                         unsigned b0, unsigned b1) {
    asm volatile("mma.sync.aligned.m16n8k16.row.col.f32.bf16.bf16.f32 "
                 "{%0,%1,%2,%3}, {%4,%5,%6,%7}, {%8,%9}, {%0,%1,%2,%3};"
                 : "+f"(c[0]), "+f"(c[1]), "+f"(c[2]), "+f"(c[3])
                 : "r"(a[0]), "r"(a[1]), "r"(a[2]), "r"(a[3]), "r"(b0), "r"(b1));
}
__device__ __forceinline__ void split_bf(float v, __nv_bfloat16& h, __nv_bfloat16& l) {
    h = __float2bfloat16_rn(v);
    l = __float2bfloat16_rn(v - __bfloat162float(h));
}
/* grid-wide barrier: monotonic counter; all 144 CTAs co-resident */
__device__ __forceinline__ void gsync(unsigned& tgt) {
    __syncthreads();
    tgt += NCTA;
    if (threadIdx.x == 0) {
        __threadfence();
        atomicAdd(&g_arrive, 1u);
        while (*(volatile unsigned*)&g_arrive < tgt) { }
    }
    __syncthreads();
}

#define RS 136
#define A_HI 0
#define A_LO (128*RS)
#define B_HI (2*128*RS)
#define B_LO (2*128*RS + 160*RS)
#define GEMM_SMEM ((2*128*RS + 2*160*RS) * 2)

__global__ void k_init() { g_arrive = 0u; }

__global__ __launch_bounds__(256,1) void k_all(const float* __restrict__ x,
                                               const float* __restrict__ W,
                                               float* __restrict__ outp) {
    extern __shared__ __align__(16) unsigned char dynsm[];
    __nv_bfloat16* sb = (__nv_bfloat16*)dynsm;
    __shared__ float c_sm[160];
    const int r = blockIdx.x;
    const int tid = threadIdx.x, w = tid >> 5, lane = tid & 31;
    const int g = lane >> 2, tg = lane & 3;
    const int nh = w >> 2, mp = w & 3;
    unsigned tgt = 0;

    /* ---------------- phase P: prep (x -> hi/lo row-major + transposed) */
    {
        float (*s)[33] = (float (*)[33])dynsm;
        const int tm = tid & 31, tr = tid >> 5;
        for (int tile = r; tile < 2304; tile += NCTA) {
            int bx = tile % 288, by = tile / 288;
            int m0 = bx*32, b0 = by*32;
            __syncthreads();
#pragma unroll
            for (int q = 0; q < 4; q++) {
                int bl = tr + q*8;
                s[bl][tm] = x[(size_t)(b0+bl)*XSTR + m0 + tm];
            }
            __syncthreads();
#pragma unroll
            for (int q = 0; q < 4; q++) {
                int bl = tr + q*8;
                float v = s[bl][tm];
                __nv_bfloat16 h, l; split_bf(v, h, l);
                size_t o = (size_t)(b0+bl)*XSTR + m0 + tm;
                g_xhi[o] = h; g_xlo[o] = l;
            }
#pragma unroll
            for (int q = 0; q < 4; q++) {
                int ml = tr + q*8;
                float v = s[tm][ml];
                __nv_bfloat16 h, l; split_bf(v, h, l);
                size_t o = (size_t)(m0+ml)*NB + b0 + tm;
                g_xthi[o] = h; g_xtlo[o] = l;
            }
        }
    }
    gsync(tgt);

    for (int it = 0; it < 3; it++) {
        /* ------------ phase G: gemm (softmax + B-build fused) */
        {
            const int mt = r & 1, ks = r >> 1;
            const int k0 = ks*128, i0 = ks*16;
            if (tid < 16) {
                int i = i0 + tid;
                float l[NJ];
                float m = -1e30f;
#pragma unroll
                for (int j = 0; j < NJ; j++) {
                    float v = 0.f;
                    for (int t = 0; t < it; t++)
                        v += __ldcg(&g_plb[t][0][i*NJ+j]) + __ldcg(&g_plb[t][1][i*NJ+j]);
                    l[j] = v; m = fmaxf(m, v);
                }
                float ssum = 0.f;
#pragma unroll
                for (int j = 0; j < NJ; j++) { l[j] = expf(l[j]-m); ssum += l[j]; }
                float inv = 1.f/ssum;
#pragma unroll
                for (int j = 0; j < NJ; j++) c_sm[tid*NJ + j] = l[j]*inv;
            }
            __syncthreads();

            for (int idx = tid; idx < 2048; idx += 256) {
                int rr = idx >> 4, c4 = idx & 15;
                size_t src = (size_t)(mt*128 + rr)*XSTR + k0 + c4*8;
                *(float4*)(sb + A_HI + rr*RS + c4*8) = *(const float4*)(g_xhi + src);
                *(float4*)(sb + A_LO + rr*RS + c4*8) = *(const float4*)(g_xlo + src);
            }
            for (int idx = tid; idx < 5120; idx += 256) {
                int il = idx / 320, rem = idx - il*320;
                int j = rem >> 5, r2 = rem & 31, d = r2 >> 1, dph = r2 & 1;
                float4 wv = *(const float4*)(W + (size_t)(i0+il)*1280 + j*128 + d*8 + dph*4);
                float c = c_sm[il*NJ + j];
                wv.x *= c; wv.y *= c; wv.z *= c; wv.w *= c;
                __nv_bfloat16 h0,h1,h2,h3,l0,l1,l2,l3;
                split_bf(wv.x,h0,l0); split_bf(wv.y,h1,l1);
                split_bf(wv.z,h2,l2); split_bf(wv.w,h3,l3);
                int off = (j*16 + d)*RS + il*8 + dph*4;
                *(__nv_bfloat162*)(sb + B_HI + off)     = __nv_bfloat162(h0,h1);
                *(__nv_bfloat162*)(sb + B_HI + off + 2) = __nv_bfloat162(h2,h3);
                *(__nv_bfloat162*)(sb + B_LO + off)     = __nv_bfloat162(l0,l1);
                *(__nv_bfloat162*)(sb + B_LO + off + 2) = __nv_bfloat162(l2,l3);
            }
            __syncthreads();

            float acc[2][10][4];
#pragma unroll
            for (int s = 0; s < 2; s++)
#pragma unroll
                for (int t = 0; t < 10; t++)
#pragma unroll
                    for (int q = 0; q < 4; q++) acc[s][t][q] = 0.f;

            const int aoffs[3] = {A_HI, A_HI, A_LO};
            const int boffs[3] = {B_HI, B_LO, B_HI};
#pragma unroll
            for (int p = 0; p < 3; p++) {
                const __nv_bfloat16* Ab = sb + aoffs[p] + (mp*32)*RS;
                const __nv_bfloat16* Bb = sb + boffs[p] + (nh*80 + g)*RS + tg*2;
#pragma unroll
                for (int kk = 0; kk < 8; kk++) {
                    unsigned a[2][4];
#pragma unroll
                    for (int s = 0; s < 2; s++) {
                        const __nv_bfloat16* ap = Ab + s*16*RS + kk*16 + tg*2;
                        a[s][0] = *(const unsigned*)(ap + g*RS);
                        a[s][1] = *(const unsigned*)(ap + (g+8)*RS);
                        a[s][2] = *(const unsigned*)(ap + g*RS + 8);
                        a[s][3] = *(const unsigned*)(ap + (g+8)*RS + 8);
                    }
#pragma unroll
                    for (int t = 0; t < 10; t++) {
                        const __nv_bfloat16* bp = Bb + t*8*RS + kk*16;
                        unsigned b0 = *(const unsigned*)(bp);
                        unsigned b1 = *(const unsigned*)(bp + 8);
                        mma16816(acc[0][t], a[0], b0, b1);
                        mma16816(acc[1][t], a[1], b0, b1);
                    }
                }
            }

            float* base = g_pp + (size_t)ks*NB*NJD;
#pragma unroll
            for (int s = 0; s < 2; s++) {
                int m0 = mt*128 + (mp*2 + s)*16;
#pragma unroll
                for (int t = 0; t < 10; t++) {
                    int jd = nh*80 + t*8 + tg*2;
                    __stcg((float2*)(base + (size_t)(m0+g)*NJD + jd),
                           make_float2(acc[s][t][0], acc[s][t][1]));
                    __stcg((float2*)(base + (size_t)(m0+g+8)*NJD + jd),
                           make_float2(acc[s][t][2], acc[s][t][3]));
                }
            }
        }
        gsync(tgt);

        /* ------------ phase R: reduce 72 partials + squash */
        if (r < 128) {
#pragma unroll
            for (int bb = 0; bb < 2; bb++) {
                int b = r*2 + bb;
                if (tid < 160) {
                    int jd = tid;
                    const float* pp = g_pp + b*NJD + jd;
                    float a0=0.f, a1=0.f, a2=0.f, a3=0.f;
#pragma unroll
                    for (int ks = 0; ks < KSPLIT; ks += 4) {
                        a0 += __ldcg(pp + (size_t)(ks+0)*NB*NJD);
                        a1 += __ldcg(pp + (size_t)(ks+1)*NB*NJD);
                        a2 += __ldcg(pp + (size_t)(ks+2)*NB*NJD);
                        a3 += __ldcg(pp + (size_t)(ks+3)*NB*NJD);
                    }
                    float v = (a0+a1) + (a2+a3);
                    float ss = v*v;
                    ss += __shfl_xor_sync(~0u, ss, 1);
                    ss += __shfl_xor_sync(~0u, ss, 2);
                    ss += __shfl_xor_sync(~0u, ss, 4);
                    ss += __shfl_xor_sync(~0u, ss, 8);
                    float f = sqrtf(ss)/(1.f + ss);
                    float rv = v*f;
                    if (it == 2) {
                        outp[b*NJD + jd] = rv;
                    } else {
                        __nv_bfloat16 h, l; split_bf(rv, h, l);
                        g_sthi[jd*NB + b] = h;
                        g_stlo[jd*NB + b] = l;
                    }
                }
            }
        }
        if (it == 2) break;
        gsync(tgt);

        /* ------------ phase A: agree (HMMA Xt*St + W contraction) */
        {
            const int a_ = r >> 1, kc = r & 1;

            for (int idx = tid; idx < 2048; idx += 256) {
                int rr = idx >> 4, c4 = idx & 15;
                size_t src = (size_t)(a_*128 + rr)*NB + kc*128 + c4*8;
                *(float4*)(sb + A_HI + rr*RS + c4*8) = *(const float4*)(g_xthi + src);
                *(float4*)(sb + A_LO + rr*RS + c4*8) = *(const float4*)(g_xtlo + src);
            }
            for (int idx = tid; idx < 2560; idx += 256) {
                int rr = idx >> 4, c4 = idx & 15;
                size_t src = (size_t)rr*NB + kc*128 + c4*8;
                *(float4*)(sb + B_HI + rr*RS + c4*8) = __ldcg((const float4*)(g_sthi + src));
                *(float4*)(sb + B_LO + rr*RS + c4*8) = __ldcg((const float4*)(g_stlo + src));
            }
            __syncthreads();

            float acc[2][10][4];
#pragma unroll
            for (int s = 0; s < 2; s++)
#pragma unroll
                for (int t = 0; t < 10; t++)
#pragma unroll
                    for (int q = 0; q < 4; q++) acc[s][t][q] = 0.f;

            const int aoffs[3] = {A_HI, A_HI, A_LO};
            const int boffs[3] = {B_HI, B_LO, B_HI};
#pragma unroll
            for (int p = 0; p < 3; p++) {
                const __nv_bfloat16* Ab = sb + aoffs[p] + (mp*32)*RS;
                const __nv_bfloat16* Bb = sb + boffs[p] + (nh*80 + g)*RS + tg*2;
#pragma unroll
                for (int kk = 0; kk < 8; kk++) {
                    unsigned a[2][4];
#pragma unroll
                    for (int s = 0; s < 2; s++) {
                        const __nv_bfloat16* ap = Ab + s*16*RS + kk*16 + tg*2;
                        a[s][0] = *(const unsigned*)(ap + g*RS);
                        a[s][1] = *(const unsigned*)(ap + (g+8)*RS);
                        a[s][2] = *(const unsigned*)(ap + g*RS + 8);
                        a[s][3] = *(const unsigned*)(ap + (g+8)*RS + 8);
                    }
#pragma unroll
                    for (int t = 0; t < 10; t++) {
                        const __nv_bfloat16* bp = Bb + t*8*RS + kk*16;
                        unsigned b0 = *(const unsigned*)(bp);
                        unsigned b1 = *(const unsigned*)(bp + 8);
                        mma16816(acc[0][t], a[0], b0, b1);
                        mma16816(acc[1][t], a[1], b0, b1);
                    }
                }
            }
            __syncthreads();

            float* At = (float*)sb;          /* [128][160] */
#pragma unroll
            for (int s = 0; s < 2; s++) {
                int m0 = (mp*2 + s)*16;
#pragma unroll
                for (int t = 0; t < 10; t++) {
                    int jd = nh*80 + t*8 + tg*2;
                    *(float2*)(At + (m0+g)*NJD + jd)   = make_float2(acc[s][t][0], acc[s][t][1]);
                    *(float2*)(At + (m0+g+8)*NJD + jd) = make_float2(acc[s][t][2], acc[s][t][3]);
                }
            }
            __syncthreads();

            if (tid < 160) {
                int il = tid / NJ, j = tid - il*NJ;
                int i = a_*16 + il;
                float accv = 0.f;
#pragma unroll
                for (int d = 0; d < 16; d++) {
                    float4 w0 = *(const float4*)(W + (size_t)i*1280 + j*128 + d*8);
                    float4 w1 = *(const float4*)(W + (size_t)i*1280 + j*128 + d*8 + 4);
                    const float* ap = At + (il*8)*NJD + j*16 + d;
                    accv += w0.x*ap[0*NJD] + w0.y*ap[1*NJD] + w0.z*ap[2*NJD] + w0.w*ap[3*NJD]
                          + w1.x*ap[4*NJD] + w1.y*ap[5*NJD] + w1.z*ap[6*NJD] + w1.w*ap[7*NJD];
                }
                __stcg(&g_plb[it][kc][i*NJ + j], accv);
            }
        }
        gsync(tgt);
    }
}

extern "C" void kernel_launch(void* const* d_in, const int* in_sizes, int n_in,
                              void* d_out, int out_size) {
    const float* x = (const float*)d_in[0];
    const float* W = (const float*)d_in[1];
    float* out = (float*)d_out;

    cudaFuncSetAttribute(k_all, cudaFuncAttributeMaxDynamicSharedMemorySize, GEMM_SMEM);

    k_init<<<1, 1>>>();
    k_all<<<NCTA, 256, GEMM_SMEM>>>(x, W, out);
}

// round 11
// speedup vs baseline: 1.2344x; 1.0654x over previous
#include <cuda_runtime.h>
#include <cuda_bf16.h>
#include <math.h>
#include <stdint.h>

#define NB 256
#define NI 1152
#define NJ 10
#define NJD 160
#define XSTR 9216
#define KSPLIT 72
#define NCTA 144

__device__ float g_pp[KSPLIT*NB*NJD];
__device__ float g_pp2[6][NB*NJD];
__device__ float g_plb[2][2][NI*NJ];             /* [iter][kchunk][i*10+j] */
__device__ __nv_bfloat16 g_xhi[NB*XSTR];         /* [b][m]  */
__device__ __nv_bfloat16 g_xlo[NB*XSTR];
__device__ __nv_bfloat16 g_xthi[XSTR*NB];        /* [m][b]  */
__device__ __nv_bfloat16 g_xtlo[XSTR*NB];
__device__ __nv_bfloat16 g_sthi[NJD*NB];         /* [jd][b] */
__device__ __nv_bfloat16 g_stlo[NJD*NB];
__device__ unsigned g_arrive;

__device__ __forceinline__ void mma16816(float* c, const unsigned* a,
                                         unsigned b0, unsigned b1) {
    asm volatile("mma.sync.aligned.m16n8k16.row.col.f32.bf16.bf16.f32 "
                 "{%0,%1,%2,%3}, {%4,%5,%6,%7}, {%8,%9}, {%0,%1,%2,%3};"
                 : "+f"(c[0]), "+f"(c[1]), "+f"(c[2]), "+f"(c[3])
                 : "r"(a[0]), "r"(a[1]), "r"(a[2]), "r"(a[3]), "r"(b0), "r"(b1));
}
__device__ __forceinline__ void split_bf(float v, __nv_bfloat16& h, __nv_bfloat16& l) {
    h = __float2bfloat16_rn(v);
    l = __float2bfloat16_rn(v - __bfloat162float(h));
}
/* grid-wide barrier: monotonic counter; all 144 CTAs co-resident */
__device__ __forceinline__ void gsync(unsigned& tgt) {
    __syncthreads();
    tgt += NCTA;
    if (threadIdx.x == 0) {
        __threadfence();
        atomicAdd(&g_arrive, 1u);
        while (*(volatile unsigned*)&g_arrive < tgt) { }
    }
    __syncthreads();
}

#define RS 136
#define A_HI 0
#define A_LO (128*RS)
#define B_HI (2*128*RS)
#define B_LO (2*128*RS + 160*RS)
#define GEMM_SMEM ((2*128*RS + 2*160*RS) * 2)

__global__ void k_init() { g_arrive = 0u; }

__global__ __launch_bounds__(256,1) void k_all(const float* __restrict__ x,
                                               const float* __restrict__ W,
                                               float* __restrict__ outp) {
    extern __shared__ __align__(16) unsigned char dynsm[];
    __nv_bfloat16* sb = (__nv_bfloat16*)dynsm;
    __shared__ float c_sm[160];
    const int r = blockIdx.x;
    const int tid = threadIdx.x, w = tid >> 5, lane = tid & 31;
    const int g = lane >> 2, tg = lane & 3;
    const int nh = w >> 2, mp = w & 3;
    unsigned tgt = 0;

    /* ---------------- phase P: prep (x -> hi/lo row-major + transposed) */
    {
        float (*s)[33] = (float (*)[33])dynsm;
        const int tm = tid & 31, tr = tid >> 5;
        for (int tile = r; tile < 2304; tile += NCTA) {
            int bx = tile % 288, by = tile / 288;
            int m0 = bx*32, b0 = by*32;
            __syncthreads();
#pragma unroll
            for (int q = 0; q < 4; q++) {
                int bl = tr + q*8;
                s[bl][tm] = x[(size_t)(b0+bl)*XSTR + m0 + tm];
            }
            __syncthreads();
#pragma unroll
            for (int q = 0; q < 4; q++) {
                int bl = tr + q*8;
                float v = s[bl][tm];
                __nv_bfloat16 h, l; split_bf(v, h, l);
                size_t o = (size_t)(b0+bl)*XSTR + m0 + tm;
                g_xhi[o] = h; g_xlo[o] = l;
            }
#pragma unroll
            for (int q = 0; q < 4; q++) {
                int ml = tr + q*8;
                float v = s[tm][ml];
                __nv_bfloat16 h, l; split_bf(v, h, l);
                size_t o = (size_t)(m0+ml)*NB + b0 + tm;
                g_xthi[o] = h; g_xtlo[o] = l;
            }
        }
    }
    gsync(tgt);

    for (int it = 0; it < 3; it++) {
        /* ------------ phase G: gemm (softmax + B-build fused) */
        {
            const int mt = r & 1, ks = r >> 1;
            const int k0 = ks*128, i0 = ks*16;
            if (tid < 16) {
                int i = i0 + tid;
                float l[NJ];
                float m = -1e30f;
#pragma unroll
                for (int j = 0; j < NJ; j++) {
                    float v = 0.f;
                    for (int t = 0; t < it; t++)
                        v += __ldcg(&g_plb[t][0][i*NJ+j]) + __ldcg(&g_plb[t][1][i*NJ+j]);
                    l[j] = v; m = fmaxf(m, v);
                }
                float ssum = 0.f;
#pragma unroll
                for (int j = 0; j < NJ; j++) { l[j] = expf(l[j]-m); ssum += l[j]; }
                float inv = 1.f/ssum;
#pragma unroll
                for (int j = 0; j < NJ; j++) c_sm[tid*NJ + j] = l[j]*inv;
            }
            __syncthreads();

            for (int idx = tid; idx < 2048; idx += 256) {
                int rr = idx >> 4, c4 = idx & 15;
                size_t src = (size_t)(mt*128 + rr)*XSTR + k0 + c4*8;
                *(float4*)(sb + A_HI + rr*RS + c4*8) = *(const float4*)(g_xhi + src);
                *(float4*)(sb + A_LO + rr*RS + c4*8) = *(const float4*)(g_xlo + src);
            }
            {
                const int il = tid >> 4, sub = tid & 15;
                const float* Wrow = W + (size_t)(i0+il)*1280;
#pragma unroll
                for (int t = 0; t < 20; t++) {
                    int rem = sub + t*16;
                    int j = rem >> 5, r2 = rem & 31, d = r2 >> 1, dph = r2 & 1;
                    float4 wv = *(const float4*)(Wrow + j*128 + d*8 + dph*4);
                    float c = c_sm[il*NJ + j];
                    wv.x *= c; wv.y *= c; wv.z *= c; wv.w *= c;
                    __nv_bfloat16 h0,h1,h2,h3,l0,l1,l2,l3;
                    split_bf(wv.x,h0,l0); split_bf(wv.y,h1,l1);
                    split_bf(wv.z,h2,l2); split_bf(wv.w,h3,l3);
                    int off = (j*16 + d)*RS + il*8 + dph*4;
                    *(__nv_bfloat162*)(sb + B_HI + off)     = __nv_bfloat162(h0,h1);
                    *(__nv_bfloat162*)(sb + B_HI + off + 2) = __nv_bfloat162(h2,h3);
                    *(__nv_bfloat162*)(sb + B_LO + off)     = __nv_bfloat162(l0,l1);
                    *(__nv_bfloat162*)(sb + B_LO + off + 2) = __nv_bfloat162(l2,l3);
                }
            }
            __syncthreads();

            float acc[2][10][4];
#pragma unroll
            for (int s = 0; s < 2; s++)
#pragma unroll
                for (int t = 0; t < 10; t++)
#pragma unroll
                    for (int q = 0; q < 4; q++) acc[s][t][q] = 0.f;

            const int aoffs[3] = {A_HI, A_HI, A_LO};
            const int boffs[3] = {B_HI, B_LO, B_HI};
#pragma unroll
            for (int p = 0; p < 3; p++) {
                const __nv_bfloat16* Ab = sb + aoffs[p] + (mp*32)*RS;
                const __nv_bfloat16* Bb = sb + boffs[p] + (nh*80 + g)*RS + tg*2;
#pragma unroll
                for (int kk = 0; kk < 8; kk++) {
                    unsigned a[2][4];
#pragma unroll
                    for (int s = 0; s < 2; s++) {
                        const __nv_bfloat16* ap = Ab + s*16*RS + kk*16 + tg*2;
                        a[s][0] = *(const unsigned*)(ap + g*RS);
                        a[s][1] = *(const unsigned*)(ap + (g+8)*RS);
                        a[s][2] = *(const unsigned*)(ap + g*RS + 8);
                        a[s][3] = *(const unsigned*)(ap + (g+8)*RS + 8);
                    }
#pragma unroll
                    for (int t = 0; t < 10; t++) {
                        const __nv_bfloat16* bp = Bb + t*8*RS + kk*16;
                        unsigned b0 = *(const unsigned*)(bp);
                        unsigned b1 = *(const unsigned*)(bp + 8);
                        mma16816(acc[0][t], a[0], b0, b1);
                        mma16816(acc[1][t], a[1], b0, b1);
                    }
                }
            }

            float* base = g_pp + (size_t)ks*NB*NJD;
#pragma unroll
            for (int s = 0; s < 2; s++) {
                int m0 = mt*128 + (mp*2 + s)*16;
#pragma unroll
                for (int t = 0; t < 10; t++) {
                    int jd = nh*80 + t*8 + tg*2;
                    __stcg((float2*)(base + (size_t)(m0+g)*NJD + jd),
                           make_float2(acc[s][t][0], acc[s][t][1]));
                    __stcg((float2*)(base + (size_t)(m0+g+8)*NJD + jd),
                           make_float2(acc[s][t][2], acc[s][t][3]));
                }
            }
        }
        gsync(tgt);

        /* ------------ phase R1: coalesced sum of 12 slices per k-chunk */
        {
            for (int idx = r*256 + tid; idx < 61440; idx += NCTA*256) {
                int kc = idx / 10240;
                int i4 = idx - kc*10240;
                const float4* bp = (const float4*)g_pp + (size_t)(kc*12)*10240 + i4;
                float4 v0 = __ldcg(bp);
                float4 v1 = __ldcg(bp + (size_t)1*10240);
                float4 v2 = __ldcg(bp + (size_t)2*10240);
                float4 v3 = __ldcg(bp + (size_t)3*10240);
                float4 v4 = __ldcg(bp + (size_t)4*10240);
                float4 v5 = __ldcg(bp + (size_t)5*10240);
                float4 v6 = __ldcg(bp + (size_t)6*10240);
                float4 v7 = __ldcg(bp + (size_t)7*10240);
                float4 v8 = __ldcg(bp + (size_t)8*10240);
                float4 v9 = __ldcg(bp + (size_t)9*10240);
                float4 va = __ldcg(bp + (size_t)10*10240);
                float4 vb = __ldcg(bp + (size_t)11*10240);
                float4 rr;
                rr.x = ((v0.x+v1.x)+(v2.x+v3.x)) + ((v4.x+v5.x)+(v6.x+v7.x)) + ((v8.x+v9.x)+(va.x+vb.x));
                rr.y = ((v0.y+v1.y)+(v2.y+v3.y)) + ((v4.y+v5.y)+(v6.y+v7.y)) + ((v8.y+v9.y)+(va.y+vb.y));
                rr.z = ((v0.z+v1.z)+(v2.z+v3.z)) + ((v4.z+v5.z)+(v6.z+v7.z)) + ((v8.z+v9.z)+(va.z+vb.z));
                rr.w = ((v0.w+v1.w)+(v2.w+v3.w)) + ((v4.w+v5.w)+(v6.w+v7.w)) + ((v8.w+v9.w)+(va.w+vb.w));
                __stcg((float4*)g_pp2[kc] + i4, rr);
            }
        }
        gsync(tgt);

        /* ------------ phase R2: sum 6 chunks + squash */
        if (r < 128) {
#pragma unroll
            for (int bb = 0; bb < 2; bb++) {
                int b = r*2 + bb;
                if (tid < 160) {
                    int jd = tid;
                    float v = 0.f;
#pragma unroll
                    for (int kc = 0; kc < 6; kc++)
                        v += __ldcg(&g_pp2[kc][b*NJD + jd]);
                    float ss = v*v;
                    ss += __shfl_xor_sync(~0u, ss, 1);
                    ss += __shfl_xor_sync(~0u, ss, 2);
                    ss += __shfl_xor_sync(~0u, ss, 4);
                    ss += __shfl_xor_sync(~0u, ss, 8);
                    float f = sqrtf(ss)/(1.f + ss);
                    float rv = v*f;
                    if (it == 2) {
                        outp[b*NJD + jd] = rv;
                    } else {
                        __nv_bfloat16 h, l; split_bf(rv, h, l);
                        g_sthi[jd*NB + b] = h;
                        g_stlo[jd*NB + b] = l;
                    }
                }
            }
        }
        if (it == 2) break;
        gsync(tgt);

        /* ------------ phase A: agree (HMMA Xt*St + W contraction) */
        {
            const int a_ = r >> 1, kc = r & 1;

            for (int idx = tid; idx < 2048; idx += 256) {
                int rr = idx >> 4, c4 = idx & 15;
                size_t src = (size_t)(a_*128 + rr)*NB + kc*128 + c4*8;
                *(float4*)(sb + A_HI + rr*RS + c4*8) = *(const float4*)(g_xthi + src);
                *(float4*)(sb + A_LO + rr*RS + c4*8) = *(const float4*)(g_xtlo + src);
            }
            for (int idx = tid; idx < 2560; idx += 256) {
                int rr = idx >> 4, c4 = idx & 15;
                size_t src = (size_t)rr*NB + kc*128 + c4*8;
                *(float4*)(sb + B_HI + rr*RS + c4*8) = __ldcg((const float4*)(g_sthi + src));
                *(float4*)(sb + B_LO + rr*RS + c4*8) = __ldcg((const float4*)(g_stlo + src));
            }
            __syncthreads();

            float acc[2][10][4];
#pragma unroll
            for (int s = 0; s < 2; s++)
#pragma unroll
                for (int t = 0; t < 10; t++)
#pragma unroll
                    for (int q = 0; q < 4; q++) acc[s][t][q] = 0.f;

            const int aoffs[3] = {A_HI, A_HI, A_LO};
            const int boffs[3] = {B_HI, B_LO, B_HI};
#pragma unroll
            for (int p = 0; p < 3; p++) {
                const __nv_bfloat16* Ab = sb + aoffs[p] + (mp*32)*RS;
                const __nv_bfloat16* Bb = sb + boffs[p] + (nh*80 + g)*RS + tg*2;
#pragma unroll
                for (int kk = 0; kk < 8; kk++) {
                    unsigned a[2][4];
#pragma unroll
                    for (int s = 0; s < 2; s++) {
                        const __nv_bfloat16* ap = Ab + s*16*RS + kk*16 + tg*2;
                        a[s][0] = *(const unsigned*)(ap + g*RS);
                        a[s][1] = *(const unsigned*)(ap + (g+8)*RS);
                        a[s][2] = *(const unsigned*)(ap + g*RS + 8);
                        a[s][3] = *(const unsigned*)(ap + (g+8)*RS + 8);
                    }
#pragma unroll
                    for (int t = 0; t < 10; t++) {
                        const __nv_bfloat16* bp = Bb + t*8*RS + kk*16;
                        unsigned b0 = *(const unsigned*)(bp);
                        unsigned b1 = *(const unsigned*)(bp + 8);
                        mma16816(acc[0][t], a[0], b0, b1);
                        mma16816(acc[1][t], a[1], b0, b1);
                    }
                }
            }
            __syncthreads();

            float* At = (float*)sb;          /* [128][160] */
#pragma unroll
            for (int s = 0; s < 2; s++) {
                int m0 = (mp*2 + s)*16;
#pragma unroll
                for (int t = 0; t < 10; t++) {
                    int jd = nh*80 + t*8 + tg*2;
                    *(float2*)(At + (m0+g)*NJD + jd)   = make_float2(acc[s][t][0], acc[s][t][1]);
                    *(float2*)(At + (m0+g+8)*NJD + jd) = make_float2(acc[s][t][2], acc[s][t][3]);
                }
            }
            __syncthreads();

            if (tid < 160) {
                int il = tid / NJ, j = tid - il*NJ;
                int i = a_*16 + il;
                float accv = 0.f;
#pragma unroll
                for (int d = 0; d < 16; d++) {
                    float4 w0 = *(const float4*)(W + (size_t)i*1280 + j*128 + d*8);
                    float4 w1 = *(const float4*)(W + (size_t)i*1280 + j*128 + d*8 + 4);
                    const float* ap = At + (il*8)*NJD + j*16 + d;
                    accv += w0.x*ap[0*NJD] + w0.y*ap[1*NJD] + w0.z*ap[2*NJD] + w0.w*ap[3*NJD]
                          + w1.x*ap[4*NJD] + w1.y*ap[5*NJD] + w1.z*ap[6*NJD] + w1.w*ap[7*NJD];
                }
                __stcg(&g_plb[it][kc][i*NJ + j], accv);
            }
        }
        gsync(tgt);
    }
}

extern "C" void kernel_launch(void* const* d_in, const int* in_sizes, int n_in,
                              void* d_out, int out_size) {
    const float* x = (const float*)d_in[0];
    const float* W = (const float*)d_in[1];
    float* out = (float*)d_out;

    cudaFuncSetAttribute(k_all, cudaFuncAttributeMaxDynamicSharedMemorySize, GEMM_SMEM);

    k_init<<<1, 1>>>();
    k_all<<<NCTA, 256, GEMM_SMEM>>>(x, W, out);
}